// round 1
// baseline (speedup 1.0000x reference)
#include <cuda_runtime.h>

// Problem constants (from reference):
//   preds: [16, 8, 17, 128, 128] f32  -> flattened N=128, K=17, H=W=128
//   gt:    [16, 8, 10, 17, 2]  f32    -> [N=128, P=10, K=17, 2]
//   out:   2 floats: (total_within, total_across)
#define N_TOT 128
#define P_NUM 10
#define K_NUM 17
#define HH 128
#define WW 128
#define INV_STRIDE 0.25f
#define NTHREADS 192

__device__ float g_within[N_TOT];
__device__ float g_across[N_TOT];
__device__ int   g_count = 0;

__global__ void __launch_bounds__(NTHREADS, 8)
group_loss_kernel(const float* __restrict__ preds,
                  const float* __restrict__ gt,
                  float* __restrict__ out) {
    const int n = blockIdx.x;
    const int t = threadIdx.x;

    __shared__ float s_val[P_NUM][K_NUM];
    __shared__ float s_msk[P_NUM][K_NUM];
    __shared__ float s_embed[P_NUM];
    __shared__ float s_cnt[P_NUM];
    __shared__ float s_wp[P_NUM];
    __shared__ int   s_last;

    // ---- Stage 1: gather scattered preds values (170 loads per block) ----
    if (t < P_NUM * K_NUM) {
        const int p = t / K_NUM;
        const int k = t % K_NUM;
        const float gx = gt[(((n * P_NUM + p) * K_NUM + k) << 1) + 0];
        const float gy = gt[(((n * P_NUM + p) * K_NUM + k) << 1) + 1];
        // jnp.round = round-half-to-even = rintf (default rounding mode)
        const int x = (int)rintf(gx * INV_STRIDE);
        const int y = (int)rintf(gy * INV_STRIDE);
        const bool valid = (x >= 0) && (x < WW) && (y >= 0) && (y < HH);
        const int xc = min(max(x, 0), WW - 1);
        const int yc = min(max(y, 0), HH - 1);
        const float v = __ldg(&preds[((n * K_NUM + k) * HH + yc) * WW + xc]);
        s_val[p][k] = valid ? v : 0.0f;
        s_msk[p][k] = valid ? 1.0f : 0.0f;
    }
    __syncthreads();

    // ---- Stage 2: per-person embed + within (threads 0..P-1) ----
    if (t < P_NUM) {
        float sum = 0.0f, cnt = 0.0f;
#pragma unroll
        for (int k = 0; k < K_NUM; k++) {
            sum += s_val[t][k];
            cnt += s_msk[t][k];
        }
        const float safe = fmaxf(cnt, 1.0f);
        const float e = sum / safe;
        float w = 0.0f;
#pragma unroll
        for (int k = 0; k < K_NUM; k++) {
            const float d = s_val[t][k] - e;
            w += d * d * s_msk[t][k];
        }
        w /= safe;
        if (!(cnt > 0.0f)) w = 0.0f;
        s_embed[t] = e;
        s_cnt[t]   = cnt;
        s_wp[t]    = w;
    }
    __syncthreads();

    // ---- Stage 3: per-n within mean + across hinge (thread 0) ----
    if (t == 0) {
        float within = 0.0f;
#pragma unroll
        for (int p = 0; p < P_NUM; p++) within += s_wp[p];
        within *= (1.0f / (float)P_NUM);

        float hinge_sum = 0.0f, denom = 0.0f;
#pragma unroll
        for (int i = 0; i < P_NUM; i++) {
            const float vi = (s_cnt[i] > 0.0f) ? 1.0f : 0.0f;
            const float ei = s_embed[i];
#pragma unroll
            for (int j = 0; j < P_NUM; j++) {
                if (i == j) continue;
                const float vj = (s_cnt[j] > 0.0f) ? 1.0f : 0.0f;
                const float pair = vi * vj;
                const float d = fabsf(s_embed[j] - ei);
                hinge_sum += fmaxf(1.0f - d, 0.0f) * pair;
                denom += pair;
            }
        }
        const float across = (denom > 0.0f) ? (hinge_sum / fmaxf(denom, 1.0f)) : 0.0f;

        g_within[n] = within;
        g_across[n] = across;
        __threadfence();
        const int done = atomicAdd(&g_count, 1);
        s_last = (done == N_TOT - 1) ? 1 : 0;
    }
    __syncthreads();

    // ---- Stage 4: last block reduces all 128 partials, writes output ----
    if (s_last) {
        __threadfence();  // acquire: make other blocks' g_* writes visible
        float w = 0.0f, a = 0.0f;
        if (t < N_TOT) {
            w = g_within[t];
            a = g_across[t];
        }
#pragma unroll
        for (int o = 16; o > 0; o >>= 1) {
            w += __shfl_down_sync(0xFFFFFFFFu, w, o);
            a += __shfl_down_sync(0xFFFFFFFFu, a, o);
        }
        __shared__ float sw[NTHREADS / 32], sa[NTHREADS / 32];
        const int warp = t >> 5, lane = t & 31;
        if (lane == 0) { sw[warp] = w; sa[warp] = a; }
        __syncthreads();
        if (t == 0) {
            float W = 0.0f, A = 0.0f;
#pragma unroll
            for (int i = 0; i < NTHREADS / 32; i++) { W += sw[i]; A += sa[i]; }
            out[0] = W * (1.0f / (float)N_TOT);  // total_within (W_WITHIN = 1)
            out[1] = A * (1.0f / (float)N_TOT);  // total_across (W_ACROSS = 1)
            g_count = 0;  // reset for next graph replay (deterministic)
        }
    }
}

extern "C" void kernel_launch(void* const* d_in, const int* in_sizes, int n_in,
                              void* d_out, int out_size) {
    const float* preds = (const float*)d_in[0];
    const float* gt    = (const float*)d_in[1];
    float* out = (float*)d_out;
    group_loss_kernel<<<N_TOT, NTHREADS>>>(preds, gt, out);
}